// round 14
// baseline (speedup 1.0000x reference)
#include <cuda_runtime.h>
#include <cuda_fp16.h>
#include <cstdint>
#include <cstddef>

// ---------------------------------------------------------------------------
// Self-attention B=8,T=2048,D=1024 fp32 in/out.
// fp16 m16n8k16 mma (fp32 accum). Persistent GEMMs, dynamic tile stealing.
// This round: fat warp tiles (64x64) -> CTA tile 256x128, 1.45x less smem
// traffic per MAC; 128x128 variant (32x64 warps) for the O-GEMM.
// ---------------------------------------------------------------------------

#define B_ 8
#define T_ 2048
#define F_ 1024

__device__ __half g_Xh  [(size_t)B_ * T_ * F_];
__device__ __half g_Wcat[(size_t)3 * F_ * F_];      // [Wq ; Wk ; Wv]
__device__ float  g_bcat[2 * F_];                   // [bq ; bk]
__device__ __half g_QKh [(size_t)B_ * T_ * 2 * F_]; // [B*T][Q|K]
__device__ __half g_VTh [(size_t)B_ * F_ * T_];     // [B][F][T]
__device__ __half g_Sh  [(size_t)B_ * T_ * T_];
__device__ unsigned g_ctrs[4];

__device__ __forceinline__ void cpa16(uint32_t dst, const void* src) {
    asm volatile("cp.async.cg.shared.global [%0], [%1], 16;" :: "r"(dst), "l"(src));
}

#define MMA_F16(d, a, b)                                                      \
    asm volatile(                                                             \
        "mma.sync.aligned.m16n8k16.row.col.f32.f16.f16.f32 "                  \
        "{%0,%1,%2,%3},{%4,%5,%6,%7},{%8,%9},{%0,%1,%2,%3};"                  \
        : "+f"(d[0]), "+f"(d[1]), "+f"(d[2]), "+f"(d[3])                      \
        : "r"(a[0]), "r"(a[1]), "r"(a[2]), "r"(a[3]), "r"(b[0]), "r"(b[1]))

#define LDSM4(r0, r1, r2, r3, addr)                                           \
    asm volatile("ldmatrix.sync.aligned.m8n8.x4.shared.b16 {%0,%1,%2,%3},[%4];" \
        : "=r"(r0), "=r"(r1), "=r"(r2), "=r"(r3) : "r"(addr))

// ---------------------------------------------------------------------------
// smem rows: 64 halfs data, stride 72 halfs (144 B). 144 mod 128 = 16 ->
// 8 consecutive rows' 16B chunks tile all 8 bank groups: conflict-free.
// ---------------------------------------------------------------------------
#define LDH     72
#define ROWB    144
#define NSTAGE  3
#define BSTG    (128 * ROWB)              // B stage bytes (N tile = 128)
#define SMEM64  (NSTAGE * (256 * ROWB + BSTG))   // 165888 (WM=64 variant)
#define SMEM32  (NSTAGE * (128 * ROWB + BSTG))   // 110592 (WM=32 variant)

// mode bits: 1=col bias, 2=row bias, 4=half output
struct Job {
    const __half* A; const __half* B; void* C; const float* bias;
    int N, K, lda, ldb, ldc;
    long long bsA, bsB, bsC;
    float alpha;
    int nx, ny, ntiles, mode;
};

__device__ __forceinline__ void epi_store(const Job* J, int tz, int r, int col,
                                          float o00, float o01, float o10, float o11)
{
    const int bm = J->mode & 3;
    if (bm == 1) {
        const float c0 = J->bias[col], c1 = J->bias[col + 1];
        o00 += c0; o01 += c1; o10 += c0; o11 += c1;
    } else if (bm == 2) {
        const float r0 = J->bias[r], r8 = J->bias[r + 8];
        o00 += r0; o01 += r0; o10 += r8; o11 += r8;
    }
    const int ldc = J->ldc;
    if (J->mode & 4) {
        __half* Cb = (__half*)J->C + (size_t)tz * J->bsC;
        *(__half2*)(Cb + (size_t)r * ldc + col)       = __floats2half2_rn(o00, o01);
        *(__half2*)(Cb + (size_t)(r + 8) * ldc + col) = __floats2half2_rn(o10, o11);
    } else {
        float* Cb = (float*)J->C + (size_t)tz * J->bsC;
        *(float2*)(Cb + (size_t)r * ldc + col)       = make_float2(o00, o01);
        *(float2*)(Cb + (size_t)(r + 8) * ldc + col) = make_float2(o10, o11);
    }
}

// ---------------------------------------------------------------------------
// CTA tile (4*WM) x 128, 8 warps in 4x2, warp tile WM x 64, BK=64 halfs.
// WM=64 -> 256x128 tile (fat), WM=32 -> 128x128 tile.
// ---------------------------------------------------------------------------
template <int WM>
__device__ __forceinline__ void tileWM(const Job* __restrict__ J,
                                       int tx, int ty, int tz,
                                       uint32_t smem_b, int tid)
{
    constexpr int TM    = 4 * WM;
    constexpr int NIM   = WM / 16;
    constexpr int ASTG  = TM * ROWB;
    constexpr int BOFF  = NSTAGE * ASTG;

    const int warp = tid >> 5, lane = tid & 31;
    const int wm = warp >> 1, wn = warp & 1;     // 4 x 2 warp grid
    const int gid = lane >> 2, tig = lane & 3;

    const int m0 = ty * TM, n0 = tx * 128;
    const int lda = J->lda, ldb = J->ldb;
    const __half* Ab = J->A + (size_t)tz * J->bsA;
    const __half* Bb = J->B + (size_t)tz * J->bsB;

    const int prow = tid >> 3;            // 0..31
    const int pch  = (tid & 7) * 8;       // halfs

    const uint32_t aBase = smem_b
        + (uint32_t)(wm * WM + (lane & 15)) * ROWB + (uint32_t)(lane >> 4) * 16u;
    const uint32_t bBase = smem_b + BOFF
        + (uint32_t)(wn * 64 + (lane & 7) + (lane >> 4) * 8) * ROWB
        + (uint32_t)((lane >> 3) & 1) * 16u;

    float acc[NIM][8][4];
#pragma unroll
    for (int i = 0; i < NIM; i++)
#pragma unroll
        for (int j = 0; j < 8; j++)
#pragma unroll
            for (int c = 0; c < 4; c++) acc[i][j][c] = 0.0f;

    const int KT = J->K >> 6;

    auto issue = [&](int kt, int st) {
        const int kb = (kt << 6) + pch;
        const uint32_t aS = smem_b + st * ASTG + prow * ROWB + (pch << 1);
        const uint32_t bS = smem_b + BOFF + st * BSTG + prow * ROWB + (pch << 1);
#pragma unroll
        for (int r = 0; r < TM / 32; r++)
            cpa16(aS + r * (32 * ROWB), Ab + (size_t)(m0 + prow + r * 32) * lda + kb);
#pragma unroll
        for (int r = 0; r < 4; r++)
            cpa16(bS + r * (32 * ROWB), Bb + (size_t)(n0 + prow + r * 32) * ldb + kb);
        asm volatile("cp.async.commit_group;");
    };

    issue(0, 0);
    issue(1, 1);

    int st = 0;
#pragma unroll 1
    for (int kt = 0; kt < KT; ++kt) {
        if (kt < KT - 1) asm volatile("cp.async.wait_group 1;");
        else             asm volatile("cp.async.wait_group 0;");
        __syncthreads();

        if (kt + 2 < KT) {
            int stw = st + 2; if (stw >= NSTAGE) stw -= NSTAGE;
            issue(kt + 2, stw);
        }

        const uint32_t aSt = aBase + st * ASTG;
        const uint32_t bSt = bBase + st * BSTG;

#pragma unroll
        for (int ks = 0; ks < 4; ++ks) {
            const uint32_t ko = ks * 32;   // 16 halfs
            uint32_t af[NIM][4], bf[8][2];
#pragma unroll
            for (int im = 0; im < NIM; im++)
                LDSM4(af[im][0], af[im][1], af[im][2], af[im][3],
                      aSt + im * (16 * ROWB) + ko);
#pragma unroll
            for (int p = 0; p < 4; p++)
                LDSM4(bf[2 * p][0], bf[2 * p][1], bf[2 * p + 1][0], bf[2 * p + 1][1],
                      bSt + p * (16 * ROWB) + ko);
#pragma unroll
            for (int im = 0; im < NIM; im++)
#pragma unroll
                for (int j = 0; j < 8; j++)
                    MMA_F16(acc[im][j], af[im], bf[j]);
        }
        if (++st >= NSTAGE) st = 0;
    }
    __syncthreads();   // all smem reads done before next tile's writes

    const float alpha = J->alpha;
#pragma unroll
    for (int im = 0; im < NIM; im++) {
        const int r = m0 + wm * WM + im * 16 + gid;
#pragma unroll
        for (int j = 0; j < 8; j++) {
            const int col = n0 + wn * 64 + j * 8 + 2 * tig;
            epi_store(J, tz, r, col,
                      alpha * acc[im][j][0], alpha * acc[im][j][1],
                      alpha * acc[im][j][2], alpha * acc[im][j][3]);
        }
    }
}

// ---------------------------------------------------------------------------
// Persistent driver over up to two jobs' tile pools
// ---------------------------------------------------------------------------
template <int WM>
__global__ __launch_bounds__(256, 1) void gemm_persist(Job j0, Job j1,
                                                       int njobs, int ctr_idx)
{
    extern __shared__ __half smem[];
    const uint32_t smem_b = (uint32_t)__cvta_generic_to_shared(smem);
    __shared__ unsigned s_t;
    const int tid = threadIdx.x;
    const unsigned total = (unsigned)(j0.ntiles + (njobs > 1 ? j1.ntiles : 0));

#pragma unroll 1
    while (true) {
        if (tid == 0) s_t = atomicAdd(&g_ctrs[ctr_idx], 1u);
        __syncthreads();
        unsigned t = s_t;
        if (t >= total) return;

        const Job* J = &j0;
        if (t >= (unsigned)j0.ntiles) { J = &j1; t -= (unsigned)j0.ntiles; }
        const unsigned per = (unsigned)(J->nx * J->ny);
        const int tz = (int)(t / per);
        const unsigned rr = t - (unsigned)tz * per;
        const int ty = (int)(rr / (unsigned)J->nx);
        const int tx = (int)(rr - (unsigned)ty * (unsigned)J->nx);

        tileWM<WM>(J, tx, ty, tz, smem_b, tid);
    }
}

// ---------------------------------------------------------------------------
__global__ void cvt_x(const float4* __restrict__ in, __half2* __restrict__ out)
{
    const int i = (blockIdx.x * blockDim.x + threadIdx.x) * 2;
    float4 a = in[i], b = in[i + 1];
    out[2 * i]     = __floats2half2_rn(a.x, a.y);
    out[2 * i + 1] = __floats2half2_rn(a.z, a.w);
    out[2 * i + 2] = __floats2half2_rn(b.x, b.y);
    out[2 * i + 3] = __floats2half2_rn(b.z, b.w);
}

__global__ void cvt_w3(const float4* __restrict__ w0, const float4* __restrict__ w1,
                       const float4* __restrict__ w2, __half2* __restrict__ out)
{
    const float4* src = (blockIdx.y == 0) ? w0 : ((blockIdx.y == 1) ? w1 : w2);
    __half2* dst = out + (size_t)blockIdx.y * (F_ * F_ / 2);
    const int i = blockIdx.x * blockDim.x + threadIdx.x;
    float4 v = src[i];
    dst[2 * i]     = __floats2half2_rn(v.x, v.y);
    dst[2 * i + 1] = __floats2half2_rn(v.z, v.w);
}

// ---------------------------------------------------------------------------
__global__ __launch_bounds__(256) void softmax2048h(__half2* __restrict__ S)
{
    __half2* p = S + ((size_t)blockIdx.y * T_ + blockIdx.x) * (T_ / 2);
    const int tid = threadIdx.x;
    __shared__ float rmax[8], rsum[8];

    float2 v[4];
    float m = -3.0e38f;
#pragma unroll
    for (int i = 0; i < 4; i++) {
        v[i] = __half22float2(p[tid + (i << 8)]);
        m = fmaxf(m, fmaxf(v[i].x, v[i].y));
    }
#pragma unroll
    for (int o = 16; o > 0; o >>= 1) m = fmaxf(m, __shfl_xor_sync(0xffffffffu, m, o));
    if ((tid & 31) == 0) rmax[tid >> 5] = m;
    __syncthreads();
    float bm = rmax[0];
#pragma unroll
    for (int i = 1; i < 8; i++) bm = fmaxf(bm, rmax[i]);

    float s = 0.0f;
#pragma unroll
    for (int i = 0; i < 4; i++) {
        v[i].x = __expf(v[i].x - bm); v[i].y = __expf(v[i].y - bm);
        s += v[i].x + v[i].y;
    }
#pragma unroll
    for (int o = 16; o > 0; o >>= 1) s += __shfl_xor_sync(0xffffffffu, s, o);
    if ((tid & 31) == 0) rsum[tid >> 5] = s;
    __syncthreads();
    float bs = 0.0f;
#pragma unroll
    for (int i = 0; i < 8; i++) bs += rsum[i];

    const float inv = 1.0f / bs;
#pragma unroll
    for (int i = 0; i < 4; i++)
        p[tid + (i << 8)] = __floats2half2_rn(v[i].x * inv, v[i].y * inv);
}

// ---------------------------------------------------------------------------
extern "C" void kernel_launch(void* const* d_in, const int* in_sizes, int n_in,
                              void* d_out, int out_size)
{
    const float* X  = (const float*)d_in[0];
    const float* Wq = (const float*)d_in[1];
    const float* bq = (const float*)d_in[2];
    const float* Wk = (const float*)d_in[3];
    const float* bk = (const float*)d_in[4];
    const float* Wv = (const float*)d_in[5];
    const float* bv = (const float*)d_in[6];
    float* O = (float*)d_out;

    __half *Xh, *Wcat, *QKh, *VTh, *Sh;
    float* bcat;
    unsigned* ctrs;
    cudaGetSymbolAddress((void**)&Xh,   g_Xh);
    cudaGetSymbolAddress((void**)&Wcat, g_Wcat);
    cudaGetSymbolAddress((void**)&bcat, g_bcat);
    cudaGetSymbolAddress((void**)&QKh,  g_QKh);
    cudaGetSymbolAddress((void**)&VTh,  g_VTh);
    cudaGetSymbolAddress((void**)&Sh,   g_Sh);
    cudaGetSymbolAddress((void**)&ctrs, g_ctrs);

    cudaFuncSetAttribute(gemm_persist<64>,
                         cudaFuncAttributeMaxDynamicSharedMemorySize, SMEM64);
    cudaFuncSetAttribute(gemm_persist<32>,
                         cudaFuncAttributeMaxDynamicSharedMemorySize, SMEM32);

    int sms = 148;
    cudaDeviceGetAttribute(&sms, cudaDevAttrMultiProcessorCount, 0);

    cudaMemsetAsync(ctrs, 0, 4 * sizeof(unsigned));

    cvt_x<<<B_ * T_ * F_ / (256 * 8), 256>>>((const float4*)X, (__half2*)Xh);
    cvt_w3<<<dim3(F_ * F_ / (256 * 4), 3), 256>>>(
        (const float4*)Wq, (const float4*)Wk, (const float4*)Wv, (__half2*)Wcat);
    cudaMemcpyAsync(bcat,      bq, F_ * sizeof(float), cudaMemcpyDeviceToDevice);
    cudaMemcpyAsync(bcat + F_, bk, F_ * sizeof(float), cudaMemcpyDeviceToDevice);

    // ---- launch A: fused QK projection + direct-VT projection (256x128) ----
    Job jQK = {};
    jQK.A = Xh;  jQK.B = Wcat; jQK.C = QKh; jQK.bias = bcat;
    jQK.N = 2 * F_; jQK.K = F_; jQK.lda = F_; jQK.ldb = F_; jQK.ldc = 2 * F_;
    jQK.bsA = 0; jQK.bsB = 0; jQK.bsC = 0;
    jQK.alpha = 1.0f; jQK.nx = 16; jQK.ny = 64; jQK.ntiles = 1024;
    jQK.mode = 1 | 4;

    Job jVT = {};
    jVT.A = Wcat + (size_t)2 * F_ * F_;  jVT.B = Xh;  jVT.C = VTh;  jVT.bias = bv;
    jVT.N = T_; jVT.K = F_; jVT.lda = F_; jVT.ldb = F_; jVT.ldc = T_;
    jVT.bsA = 0; jVT.bsB = (long long)T_ * F_; jVT.bsC = (long long)F_ * T_;
    jVT.alpha = 1.0f; jVT.nx = 16; jVT.ny = 4; jVT.ntiles = 8 * 16 * 4;
    jVT.mode = 2 | 4;

    gemm_persist<64><<<sms, 256, SMEM64>>>(jQK, jVT, 2, 0);

    // ---- launch B: scores S = (Q K^T)/32 (256x128) ----
    Job jS = {};
    jS.A = QKh;  jS.B = QKh + F_;  jS.C = Sh;  jS.bias = nullptr;
    jS.N = T_; jS.K = F_; jS.lda = 2 * F_; jS.ldb = 2 * F_; jS.ldc = T_;
    jS.bsA = (long long)T_ * 2 * F_; jS.bsB = (long long)T_ * 2 * F_;
    jS.bsC = (long long)T_ * T_;
    jS.alpha = 0.03125f; jS.nx = 16; jS.ny = 8; jS.ntiles = 8 * 16 * 8;
    jS.mode = 4;

    gemm_persist<64><<<sms, 256, SMEM64>>>(jS, jS, 1, 1);

    softmax2048h<<<dim3(T_, B_), 256>>>((__half2*)Sh);

    // ---- launch C: O = P @ VT^T (fp32 out), 128x128 tiles ----
    Job jO = {};
    jO.A = Sh;  jO.B = VTh;  jO.C = O;  jO.bias = nullptr;
    jO.N = F_; jO.K = T_; jO.lda = T_; jO.ldb = T_; jO.ldc = F_;
    jO.bsA = (long long)T_ * T_; jO.bsB = (long long)F_ * T_;
    jO.bsC = (long long)T_ * F_;
    jO.alpha = 1.0f; jO.nx = 8; jO.ny = 16; jO.ntiles = 8 * 16 * 8;
    jO.mode = 0;

    gemm_persist<32><<<sms, 256, SMEM32>>>(jO, jO, 1, 2);
}